// round 17
// baseline (speedup 1.0000x reference)
#include <cuda_runtime.h>
#include <cuda_bf16.h>
#include <cstdint>

#define Bc 8
#define Sc 384
#define Dc 1024
#define Hc 16
#define HDc 64
#define D3c 3072
#define BSc 3072   // B*S
#define RPE_ROWS 1023

// ---------------------------------------------------------------------------
// Scratch (static device globals; no runtime allocation)
// ---------------------------------------------------------------------------
__device__ float g_attn[(size_t)Bc * Hc * Sc * Sc];   // fallback attn buffer
__device__ __align__(16) __nv_bfloat16 g_ah[(size_t)BSc * Dc];    // A hi (x, then vals)
__device__ __align__(16) __nv_bfloat16 g_al[(size_t)BSc * Dc];    // A lo
__device__ __align__(16) __nv_bfloat16 g_wqh[(size_t)D3c * Dc];   // qkv_w^T hi [N,K]
__device__ __align__(16) __nv_bfloat16 g_wql[(size_t)D3c * Dc];   // qkv_w^T lo
__device__ __align__(16) __nv_bfloat16 g_woh[(size_t)Dc * Dc];    // out_w^T hi
__device__ __align__(16) __nv_bfloat16 g_wol[(size_t)Dc * Dc];    // out_w^T lo
__device__ __align__(16) __nv_bfloat16 g_qkvh[(size_t)BSc * D3c]; // qkv hi (q pre-scaled /8)
__device__ __align__(16) __nv_bfloat16 g_qkvl[(size_t)BSc * D3c]; // qkv lo
__device__ __align__(16) __nv_bfloat16 g_rpeh[(size_t)RPE_ROWS * Dc]; // rpe hi
__device__ __align__(16) __nv_bfloat16 g_rpel[(size_t)RPE_ROWS * Dc]; // rpe lo

// ---------------------------------------------------------------------------
// Baseline-PTX helpers
// ---------------------------------------------------------------------------
__device__ __forceinline__ uint32_t smem_u32(const void* p) {
    uint32_t a;
    asm("{ .reg .u64 t; cvta.to.shared.u64 t, %1; cvt.u32.u64 %0, t; }" : "=r"(a) : "l"(p));
    return a;
}
#define CP_ASYNC16(sm, gp) \
    asm volatile("cp.async.cg.shared.global [%0], [%1], 16;" :: "r"(sm), "l"(gp))
#define CP_COMMIT() asm volatile("cp.async.commit_group;" ::: "memory")
#define CP_WAIT0()  asm volatile("cp.async.wait_group 0;" ::: "memory")
#define CP_WAIT1()  asm volatile("cp.async.wait_group 1;" ::: "memory")

#define LDSM_X4(r, a) \
    asm volatile("ldmatrix.sync.aligned.m8n8.x4.shared.b16 {%0,%1,%2,%3}, [%4];" \
        : "=r"((r)[0]), "=r"((r)[1]), "=r"((r)[2]), "=r"((r)[3]) : "r"(a))
#define LDSM_X4_T(r, a) \
    asm volatile("ldmatrix.sync.aligned.m8n8.x4.trans.shared.b16 {%0,%1,%2,%3}, [%4];" \
        : "=r"((r)[0]), "=r"((r)[1]), "=r"((r)[2]), "=r"((r)[3]) : "r"(a))

__device__ __forceinline__ void mma_bf16(float* d, const uint32_t* a,
                                         uint32_t b0, uint32_t b1) {
    asm volatile(
        "mma.sync.aligned.m16n8k16.row.col.f32.bf16.bf16.f32 "
        "{%0,%1,%2,%3}, {%4,%5,%6,%7}, {%8,%9}, {%0,%1,%2,%3};"
        : "+f"(d[0]), "+f"(d[1]), "+f"(d[2]), "+f"(d[3])
        : "r"(a[0]), "r"(a[1]), "r"(a[2]), "r"(a[3]), "r"(b0), "r"(b1));
}

__device__ __forceinline__ void split2(float x, float y,
                                       __nv_bfloat16* ph, __nv_bfloat16* pl) {
    __nv_bfloat16 hx = __float2bfloat16(x), hy = __float2bfloat16(y);
    *(__nv_bfloat162*)ph = __nv_bfloat162(hx, hy);
    *(__nv_bfloat162*)pl = __nv_bfloat162(
        __float2bfloat16(x - __bfloat162float(hx)),
        __float2bfloat16(y - __bfloat162float(hy)));
}
__device__ __forceinline__ void pack_hilo(float x, float y,
                                          uint32_t& hi, uint32_t& lo) {
    __nv_bfloat16 hx = __float2bfloat16(x), hy = __float2bfloat16(y);
    __nv_bfloat162 h2(hx, hy);
    __nv_bfloat162 l2(__float2bfloat16(x - __bfloat162float(hx)),
                      __float2bfloat16(y - __bfloat162float(hy)));
    hi = *(uint32_t*)&h2;
    lo = *(uint32_t*)&l2;
}

// ---------------------------------------------------------------------------
// HMMA bf16-split GEMM (128x128 tile): used for the big qkv projection.
// ---------------------------------------------------------------------------
#define TILE_B 8192
#define BUF_B  (4 * TILE_B)
#define NSTAGE 3
#define GSMEM  (NSTAGE * BUF_B)   // 96 KB

__global__ __launch_bounds__(256, 2) void mma_gemm_kernel(
    const __nv_bfloat16* __restrict__ Ah, const __nv_bfloat16* __restrict__ Al,
    const __nv_bfloat16* __restrict__ Bh, const __nv_bfloat16* __restrict__ Bl,
    const float* __restrict__ bias, float* __restrict__ C,
    __nv_bfloat16* __restrict__ Ch, __nv_bfloat16* __restrict__ Cl,
    int qkv_mode, int M, int N, int K)
{
    extern __shared__ char smem[];
    const uint32_t sbase = smem_u32(smem);
    const int tid  = threadIdx.x;
    const int wid  = tid >> 5;
    const int lane = tid & 31;
    const int m0 = blockIdx.y * 128;
    const int n0 = blockIdx.x * 128;
    const int mw = (wid & 1) * 64;
    const int nw = (wid >> 1) * 32;

    const int lrow = tid >> 1;
    const int c0   = (tid & 1) * 2;
    const int sw0  = (lrow >> 1) & 3;
    const __nv_bfloat16* gAh = Ah + (size_t)(m0 + lrow) * K;
    const __nv_bfloat16* gAl = Al + (size_t)(m0 + lrow) * K;
    const __nv_bfloat16* gBh = Bh + (size_t)(n0 + lrow) * K;
    const __nv_bfloat16* gBl = Bl + (size_t)(n0 + lrow) * K;
    const uint32_t soff0 = lrow * 64 + (((c0 + 0) ^ sw0) << 4);
    const uint32_t soff1 = lrow * 64 + (((c0 + 1) ^ sw0) << 4);

    const int NK = K >> 5;

    auto issue = [&](int it) {
        if (it < NK) {
            const uint32_t tb = sbase + (it % NSTAGE) * BUF_B;
            const int k0 = it << 5;
            CP_ASYNC16(tb + 0 * TILE_B + soff0, gAh + k0 + (c0 + 0) * 8);
            CP_ASYNC16(tb + 0 * TILE_B + soff1, gAh + k0 + (c0 + 1) * 8);
            CP_ASYNC16(tb + 1 * TILE_B + soff0, gAl + k0 + (c0 + 0) * 8);
            CP_ASYNC16(tb + 1 * TILE_B + soff1, gAl + k0 + (c0 + 1) * 8);
            CP_ASYNC16(tb + 2 * TILE_B + soff0, gBh + k0 + (c0 + 0) * 8);
            CP_ASYNC16(tb + 2 * TILE_B + soff1, gBh + k0 + (c0 + 1) * 8);
            CP_ASYNC16(tb + 3 * TILE_B + soff0, gBl + k0 + (c0 + 0) * 8);
            CP_ASYNC16(tb + 3 * TILE_B + soff1, gBl + k0 + (c0 + 1) * 8);
        }
        CP_COMMIT();
    };

    const int frow = lane & 15;
    const int fc   = lane >> 4;
    auto fr_addr = [&](int rbase) -> uint32_t {
        const int row = rbase + frow;
        return (uint32_t)(row * 64 + ((fc ^ ((row >> 1) & 3)) << 4));
    };
    const uint32_t aoff = fr_addr(mw);
    const uint32_t boff = fr_addr(nw);

    float acc[4][4][4];
    #pragma unroll
    for (int i = 0; i < 4; i++)
        #pragma unroll
        for (int j = 0; j < 4; j++)
            #pragma unroll
            for (int r = 0; r < 4; r++) acc[i][j][r] = 0.f;

    issue(0); issue(1);

    for (int it = 0; it < NK; it++) {
        CP_WAIT1();
        __syncthreads();
        issue(it + 2);
        const uint32_t tb = sbase + (it % NSTAGE) * BUF_B;
        #pragma unroll
        for (int ks = 0; ks < 2; ks++) {
            const uint32_t kx = ks ? 32u : 0u;
            uint32_t ahf[4][4], bhf[2][4];
            #pragma unroll
            for (int mt = 0; mt < 4; mt++)
                LDSM_X4(ahf[mt], tb + ((aoff + mt * 1024) ^ kx));
            #pragma unroll
            for (int bt = 0; bt < 2; bt++)
                LDSM_X4(bhf[bt], tb + 2 * TILE_B + ((boff + bt * 1024) ^ kx));
            #pragma unroll
            for (int mt = 0; mt < 4; mt++)
                #pragma unroll
                for (int nt = 0; nt < 4; nt++)
                    mma_bf16(acc[mt][nt], ahf[mt],
                             bhf[nt >> 1][nt & 1], bhf[nt >> 1][(nt & 1) + 2]);
            uint32_t blf[2][4];
            #pragma unroll
            for (int bt = 0; bt < 2; bt++)
                LDSM_X4(blf[bt], tb + 3 * TILE_B + ((boff + bt * 1024) ^ kx));
            #pragma unroll
            for (int mt = 0; mt < 4; mt++)
                #pragma unroll
                for (int nt = 0; nt < 4; nt++)
                    mma_bf16(acc[mt][nt], ahf[mt],
                             blf[nt >> 1][nt & 1], blf[nt >> 1][(nt & 1) + 2]);
            uint32_t alf[4][4];
            #pragma unroll
            for (int mt = 0; mt < 4; mt++)
                LDSM_X4(alf[mt], tb + TILE_B + ((aoff + mt * 1024) ^ kx));
            #pragma unroll
            for (int mt = 0; mt < 4; mt++)
                #pragma unroll
                for (int nt = 0; nt < 4; nt++)
                    mma_bf16(acc[mt][nt], alf[mt],
                             bhf[nt >> 1][nt & 1], bhf[nt >> 1][(nt & 1) + 2]);
        }
    }

    const int er = lane >> 2;
    const int ec = (lane & 3) * 2;
    #pragma unroll
    for (int mt = 0; mt < 4; mt++) {
        #pragma unroll
        for (int nt = 0; nt < 4; nt++) {
            const int col = n0 + nw + nt * 8 + ec;
            const float bx = __ldg(&bias[col]);
            const float by = __ldg(&bias[col + 1]);
            const int r0 = m0 + mw + mt * 16 + er;
            float2 v0 = make_float2(acc[mt][nt][0] + bx, acc[mt][nt][1] + by);
            float2 v1 = make_float2(acc[mt][nt][2] + bx, acc[mt][nt][3] + by);
            if (C) {
                *(float2*)(C + (size_t)r0 * N + col) = v0;
                *(float2*)(C + (size_t)(r0 + 8) * N + col) = v1;
            }
            if (Ch) {
                const float s = (qkv_mode && (((col >> 6) % 3) == 0)) ? 0.125f : 1.0f;
                split2(v0.x * s, v0.y * s, Ch + (size_t)r0 * N + col,
                       Cl + (size_t)r0 * N + col);
                split2(v1.x * s, v1.y * s, Ch + (size_t)(r0 + 8) * N + col,
                       Cl + (size_t)(r0 + 8) * N + col);
            }
        }
    }
}

// ---------------------------------------------------------------------------
// out-proj GEMM: 64x128 tile, 3 CTA/SM (wave-balance fix from R16).
// ---------------------------------------------------------------------------
#define OTILE_A 4096
#define OTILE_B 8192
#define OBUF    (2 * OTILE_A + 2 * OTILE_B)   // 24576
#define OSMEM   (NSTAGE * OBUF)               // 73728

__global__ __launch_bounds__(256, 3) void out_gemm_kernel(
    const __nv_bfloat16* __restrict__ Ah, const __nv_bfloat16* __restrict__ Al,
    const __nv_bfloat16* __restrict__ Bh, const __nv_bfloat16* __restrict__ Bl,
    const float* __restrict__ bias, float* __restrict__ C,
    int M, int N, int K)
{
    extern __shared__ char smem[];
    const uint32_t sbase = smem_u32(smem);
    const int tid  = threadIdx.x;
    const int wid  = tid >> 5;
    const int lane = tid & 31;
    const int m0 = blockIdx.y * 64;
    const int n0 = blockIdx.x * 128;
    const int mw = (wid & 1) * 32;
    const int nw = (wid >> 1) * 32;

    const int arow_l = tid >> 2;
    const int ac     = tid & 3;
    const uint32_t soffA = arow_l * 64 + ((ac ^ ((arow_l >> 1) & 3)) << 4);
    const __nv_bfloat16* gAh = Ah + (size_t)(m0 + arow_l) * K;
    const __nv_bfloat16* gAl = Al + (size_t)(m0 + arow_l) * K;
    const int lrow = tid >> 1;
    const int c0   = (tid & 1) * 2;
    const int sw0  = (lrow >> 1) & 3;
    const __nv_bfloat16* gBh = Bh + (size_t)(n0 + lrow) * K;
    const __nv_bfloat16* gBl = Bl + (size_t)(n0 + lrow) * K;
    const uint32_t soff0 = lrow * 64 + (((c0 + 0) ^ sw0) << 4);
    const uint32_t soff1 = lrow * 64 + (((c0 + 1) ^ sw0) << 4);

    const int NK = K >> 5;

    auto issue = [&](int it) {
        if (it < NK) {
            const uint32_t tb = sbase + (it % NSTAGE) * OBUF;
            const int k0 = it << 5;
            CP_ASYNC16(tb + 0 * OTILE_A + soffA, gAh + k0 + ac * 8);
            CP_ASYNC16(tb + 1 * OTILE_A + soffA, gAl + k0 + ac * 8);
            CP_ASYNC16(tb + 2 * OTILE_A + soff0, gBh + k0 + (c0 + 0) * 8);
            CP_ASYNC16(tb + 2 * OTILE_A + soff1, gBh + k0 + (c0 + 1) * 8);
            CP_ASYNC16(tb + 2 * OTILE_A + OTILE_B + soff0, gBl + k0 + (c0 + 0) * 8);
            CP_ASYNC16(tb + 2 * OTILE_A + OTILE_B + soff1, gBl + k0 + (c0 + 1) * 8);
        }
        CP_COMMIT();
    };

    const int frow = lane & 15;
    const int fc   = lane >> 4;
    auto fr_addr = [&](int rbase) -> uint32_t {
        const int row = rbase + frow;
        return (uint32_t)(row * 64 + ((fc ^ ((row >> 1) & 3)) << 4));
    };
    const uint32_t aoff = fr_addr(mw);
    const uint32_t boff = fr_addr(nw);

    float acc[2][4][4];
    #pragma unroll
    for (int i = 0; i < 2; i++)
        #pragma unroll
        for (int j = 0; j < 4; j++)
            #pragma unroll
            for (int r = 0; r < 4; r++) acc[i][j][r] = 0.f;

    issue(0); issue(1);

    for (int it = 0; it < NK; it++) {
        CP_WAIT1();
        __syncthreads();
        issue(it + 2);
        const uint32_t tb = sbase + (it % NSTAGE) * OBUF;
        #pragma unroll
        for (int ks = 0; ks < 2; ks++) {
            const uint32_t kx = ks ? 32u : 0u;
            uint32_t ahf[2][4], bhf[2][4];
            #pragma unroll
            for (int mt = 0; mt < 2; mt++)
                LDSM_X4(ahf[mt], tb + ((aoff + mt * 1024) ^ kx));
            #pragma unroll
            for (int bt = 0; bt < 2; bt++)
                LDSM_X4(bhf[bt], tb + 2 * OTILE_A + ((boff + bt * 1024) ^ kx));
            #pragma unroll
            for (int mt = 0; mt < 2; mt++)
                #pragma unroll
                for (int nt = 0; nt < 4; nt++)
                    mma_bf16(acc[mt][nt], ahf[mt],
                             bhf[nt >> 1][nt & 1], bhf[nt >> 1][(nt & 1) + 2]);
            uint32_t blf[2][4];
            #pragma unroll
            for (int bt = 0; bt < 2; bt++)
                LDSM_X4(blf[bt], tb + 2 * OTILE_A + OTILE_B + ((boff + bt * 1024) ^ kx));
            #pragma unroll
            for (int mt = 0; mt < 2; mt++)
                #pragma unroll
                for (int nt = 0; nt < 4; nt++)
                    mma_bf16(acc[mt][nt], ahf[mt],
                             blf[nt >> 1][nt & 1], blf[nt >> 1][(nt & 1) + 2]);
            uint32_t alf[2][4];
            #pragma unroll
            for (int mt = 0; mt < 2; mt++)
                LDSM_X4(alf[mt], tb + OTILE_A + ((aoff + mt * 1024) ^ kx));
            #pragma unroll
            for (int mt = 0; mt < 2; mt++)
                #pragma unroll
                for (int nt = 0; nt < 4; nt++)
                    mma_bf16(acc[mt][nt], alf[mt],
                             bhf[nt >> 1][nt & 1], bhf[nt >> 1][(nt & 1) + 2]);
        }
    }

    const int er = lane >> 2;
    const int ec = (lane & 3) * 2;
    #pragma unroll
    for (int mt = 0; mt < 2; mt++) {
        #pragma unroll
        for (int nt = 0; nt < 4; nt++) {
            const int col = n0 + nw + nt * 8 + ec;
            const float bx = __ldg(&bias[col]);
            const float by = __ldg(&bias[col + 1]);
            const int r0 = m0 + mw + mt * 16 + er;
            *(float2*)(C + (size_t)r0 * N + col) =
                make_float2(acc[mt][nt][0] + bx, acc[mt][nt][1] + by);
            *(float2*)(C + (size_t)(r0 + 8) * N + col) =
                make_float2(acc[mt][nt][2] + bx, acc[mt][nt][3] + by);
        }
    }
}

// ---------------------------------------------------------------------------
// Fused prep: split x + transpose-split qkv_w + out_w + split rpe table.
// ---------------------------------------------------------------------------
__global__ __launch_bounds__(256) void prep_kernel(
    const float* __restrict__ x,
    __nv_bfloat16* __restrict__ ah, __nv_bfloat16* __restrict__ al,
    const float* __restrict__ qkv_w,
    __nv_bfloat16* __restrict__ wqh, __nv_bfloat16* __restrict__ wql,
    const float* __restrict__ out_w,
    __nv_bfloat16* __restrict__ woh, __nv_bfloat16* __restrict__ wol,
    const float* __restrict__ rpe,
    __nv_bfloat16* __restrict__ rpeh, __nv_bfloat16* __restrict__ rpel)
{
    __shared__ float t[32][33];
    const int bid = blockIdx.x;
    const int tid = threadIdx.x;
    if (bid < 3072) {
        const int i = bid * 256 + tid;
        float4 v = ((const float4*)x)[i];
        split2(v.x, v.y, ah + 4 * (size_t)i, al + 4 * (size_t)i);
        split2(v.z, v.w, ah + 4 * (size_t)i + 2, al + 4 * (size_t)i + 2);
        return;
    }
    if (bid >= 7168) {
        const int i = (bid - 7168) * 256 + tid;
        float4 v = ((const float4*)rpe)[i];
        split2(v.x, v.y, rpeh + 4 * (size_t)i, rpel + 4 * (size_t)i);
        split2(v.z, v.w, rpeh + 4 * (size_t)i + 2, rpel + 4 * (size_t)i + 2);
        return;
    }
    const float* W;
    __nv_bfloat16 *Th, *Tl;
    int N, bx, by;
    if (bid < 6144) {
        const int r = bid - 3072;
        W = qkv_w; Th = wqh; Tl = wql; N = D3c;
        bx = r % 96; by = r / 96;
    } else {
        const int r = bid - 6144;
        W = out_w; Th = woh; Tl = wol; N = Dc;
        bx = r % 32; by = r / 32;
    }
    const int K = Dc;
    const int n0 = bx * 32, k0 = by * 32;
    const int tx = tid & 31, ty = tid >> 5;
    #pragma unroll
    for (int r = 0; r < 4; r++)
        t[ty + 8 * r][tx] = W[(size_t)(k0 + ty + 8 * r) * N + n0 + tx];
    __syncthreads();
    #pragma unroll
    for (int r = 0; r < 4; r++) {
        float v = t[tx][ty + 8 * r];
        __nv_bfloat16 h = __float2bfloat16(v);
        __nv_bfloat16 l = __float2bfloat16(v - __bfloat162float(h));
        size_t o = (size_t)(n0 + ty + 8 * r) * K + k0 + tx;
        Th[o] = h; Tl[o] = l;
    }
}

// ---------------------------------------------------------------------------
// qk HMMA: logits = (scaled q).k, 3-pass bf16 split, interleaved LDSM.
// ---------------------------------------------------------------------------
#define QK_SMEM (4 * 16384)

__global__ __launch_bounds__(256, 2) void qk_mma_kernel(
    const __nv_bfloat16* __restrict__ qkvh, const __nv_bfloat16* __restrict__ qkvl,
    float* __restrict__ attn)
{
    extern __shared__ char smem[];
    const uint32_t sb = smem_u32(smem);
    const int tid = threadIdx.x, wid = tid >> 5, lane = tid & 31;
    const int bh = blockIdx.z, b = bh >> 4, h = bh & 15;
    const int i0 = blockIdx.y * 128, j0 = blockIdx.x * 128;

    #pragma unroll
    for (int t = 0; t < 4; t++) {
        const __nv_bfloat16* base = (t & 1) ? qkvl : qkvh;
        const int roff = (t < 2) ? i0 : j0;
        const int coff = h * 192 + ((t < 2) ? 0 : 64);
        for (int idx = tid; idx < 1024; idx += 256) {
            const int row = idx >> 3, c = idx & 7;
            const uint32_t dst = sb + t * 16384 + row * 128 + ((c ^ (row & 7)) << 4);
            CP_ASYNC16(dst, base + (size_t)(b * Sc + roff + row) * D3c + coff + c * 8);
        }
    }
    CP_COMMIT(); CP_WAIT0();
    __syncthreads();

    const int mw = (wid & 1) * 64;
    const int nw = (wid >> 1) * 32;
    const int frow = lane & 15, fc = lane >> 4;

    float acc[4][4][4];
    #pragma unroll
    for (int i = 0; i < 4; i++)
        #pragma unroll
        for (int j = 0; j < 4; j++)
            #pragma unroll
            for (int r = 0; r < 4; r++) acc[i][j][r] = 0.f;

    #pragma unroll
    for (int ks = 0; ks < 4; ks++) {
        uint32_t aadr[4], badr[2];
        #pragma unroll
        for (int mt = 0; mt < 4; mt++) {
            const int row = mw + mt * 16 + frow;
            aadr[mt] = row * 128 + (((2 * ks + fc) ^ (row & 7)) << 4);
        }
        #pragma unroll
        for (int bt = 0; bt < 2; bt++) {
            const int row = nw + bt * 16 + frow;
            badr[bt] = row * 128 + (((2 * ks + fc) ^ (row & 7)) << 4);
        }
        uint32_t ahf[4][4], bhf[2][4];
        #pragma unroll
        for (int mt = 0; mt < 4; mt++) LDSM_X4(ahf[mt], sb + aadr[mt]);
        #pragma unroll
        for (int bt = 0; bt < 2; bt++) LDSM_X4(bhf[bt], sb + 2 * 16384 + badr[bt]);
        #pragma unroll
        for (int mt = 0; mt < 4; mt++)
            #pragma unroll
            for (int nt = 0; nt < 4; nt++)
                mma_bf16(acc[mt][nt], ahf[mt],
                         bhf[nt >> 1][nt & 1], bhf[nt >> 1][(nt & 1) + 2]);
        uint32_t blf[2][4];
        #pragma unroll
        for (int bt = 0; bt < 2; bt++) LDSM_X4(blf[bt], sb + 3 * 16384 + badr[bt]);
        #pragma unroll
        for (int mt = 0; mt < 4; mt++)
            #pragma unroll
            for (int nt = 0; nt < 4; nt++)
                mma_bf16(acc[mt][nt], ahf[mt],
                         blf[nt >> 1][nt & 1], blf[nt >> 1][(nt & 1) + 2]);
        uint32_t alf[4][4];
        #pragma unroll
        for (int mt = 0; mt < 4; mt++) LDSM_X4(alf[mt], sb + 16384 + aadr[mt]);
        #pragma unroll
        for (int mt = 0; mt < 4; mt++)
            #pragma unroll
            for (int nt = 0; nt < 4; nt++)
                mma_bf16(acc[mt][nt], alf[mt],
                         bhf[nt >> 1][nt & 1], bhf[nt >> 1][(nt & 1) + 2]);
    }

    const int er = lane >> 2, ec = (lane & 3) * 2;
    float* ob = attn + (size_t)bh * Sc * Sc;
    #pragma unroll
    for (int mt = 0; mt < 4; mt++) {
        #pragma unroll
        for (int nt = 0; nt < 4; nt++) {
            const int r0 = i0 + mw + mt * 16 + er;
            const int col = j0 + nw + nt * 8 + ec;
            *(float2*)(ob + (size_t)r0 * Sc + col) =
                make_float2(acc[mt][nt][0], acc[mt][nt][1]);
            *(float2*)(ob + (size_t)(r0 + 8) * Sc + col) =
                make_float2(acc[mt][nt][2], acc[mt][nt][3]);
        }
    }
}

// ---------------------------------------------------------------------------
// rpe bias via HMMA + fused softmax — 4 same-slab items per block, 3 CTA/SM.
// R17: attn read DIRECTLY from gmem in the bias-add (no L-prefetch path):
// L becomes store-only during accumulation, cutting L1 wavefront pressure.
// SMEM: q 8KB | slab 16KB | L 48KB = 73728 B.
// ---------------------------------------------------------------------------
#define RPE_SMEM (8192 + 16384 + 32 * Sc * 4)   // 73728

__global__ __launch_bounds__(256, 3) void rpe_mma_softmax_kernel(
    const __nv_bfloat16* __restrict__ qkvh, const __nv_bfloat16* __restrict__ qkvl,
    const __nv_bfloat16* __restrict__ rpeh, const __nv_bfloat16* __restrict__ rpel,
    float* __restrict__ attn)
{
    extern __shared__ char smem[];
    const uint32_t sb = smem_u32(smem);
    const uint32_t slab0 = sb + 8192;
    float* L = (float*)(smem + 8192 + 16384);     // [32][384]
    const int tid = threadIdx.x, wid = tid >> 5, lane = tid & 31;

    const int a = blockIdx.x / 31;
    const int d = blockIdx.x % 31 - 15;
    const int h_lo = d < 0 ? -d : 0;
    const int h_hi = d > 0 ? 15 - d : 15;
    const int h0 = h_lo + 4 * (int)blockIdx.y;
    if (h0 > h_hi) return;
    int hh[4], ii[4];
    #pragma unroll
    for (int it = 0; it < 4; it++) {
        const int hx = (h0 + it <= h_hi) ? (h0 + it) : h_hi;
        hh[it] = hx;
        ii[it] = 16 * a + hx + d;
    }
    const size_t r0off = (size_t)(384 + 24 * d - a) * 1024;

    // hoisted slab loader addresses: 2 chunks per thread
    const int srow0 = tid >> 3,        sc0 = tid & 7;
    const int srow1 = (tid + 256) >> 3, sc1 = (tid + 256) & 7;
    const uint32_t ssw0 = srow0 * 128 + ((sc0 ^ (srow0 & 7)) << 4);
    const uint32_t ssw1 = srow1 * 128 + ((sc1 ^ (srow1 & 7)) << 4);
    const __nv_bfloat16* sph0 = rpeh + r0off + (size_t)srow0 * 64 + sc0 * 8;
    const __nv_bfloat16* spl0 = rpel + r0off + (size_t)srow0 * 64 + sc0 * 8;
    const __nv_bfloat16* sph1 = rpeh + r0off + (size_t)srow1 * 64 + sc1 * 8;
    const __nv_bfloat16* spl1 = rpel + r0off + (size_t)srow1 * 64 + sc1 * 8;

    auto slab_issue = [&](int nc) {
        const int off = nc * 4096;
        CP_ASYNC16(slab0 + ssw0, sph0 + off);
        CP_ASYNC16(slab0 + 8192 + ssw0, spl0 + off);
        CP_ASYNC16(slab0 + ssw1, sph1 + off);
        CP_ASYNC16(slab0 + 8192 + ssw1, spl1 + off);
        CP_COMMIT();
    };

    // q tiles (2 arrays x 32 rows x 8 chunks)
    for (int t = tid; t < 512; t += 256) {
        const int arr = t >> 8;
        const int r = (t >> 3) & 31;
        const int c = t & 7;
        const int it = r >> 3, b = r & 7;
        const __nv_bfloat16* src = arr ? qkvl : qkvh;
        CP_ASYNC16(sb + arr * 4096 + r * 128 + ((c ^ (r & 7)) << 4),
                   src + (size_t)(b * Sc + ii[it]) * D3c + hh[it] * 192 + c * 8);
    }
    CP_COMMIT();

    const int frow = lane & 15, fc = lane >> 4;
    const int mt = wid >> 2;               // m16 tile 0/1
    const int wn = (wid & 3) * 16;
    const int er = lane >> 2, ec = (lane & 3) * 2;
    const int arow = mt * 16 + frow;

    // hoisted attn row pointers for the bias-add (items 2mt / 2mt+1, batch er)
    const float* arow0 = attn + ((size_t)(er * Hc + hh[2 * mt]) * Sc + ii[2 * mt]) * Sc;
    const float* arow1 = attn + ((size_t)(er * Hc + hh[2 * mt + 1]) * Sc + ii[2 * mt + 1]) * Sc;

    for (int ck = 0; ck < 6; ck++) {
        slab_issue(ck);
        CP_WAIT0();
        __syncthreads();
        float acc[2][4];
        #pragma unroll
        for (int nt = 0; nt < 2; nt++)
            #pragma unroll
            for (int r = 0; r < 4; r++) acc[nt][r] = 0.f;

        #pragma unroll
        for (int ks = 0; ks < 4; ks++) {
            const uint32_t aadr = arow * 128 + (((2 * ks + fc) ^ (arow & 7)) << 4);
            const int brow = wn + frow;
            const uint32_t badr = brow * 128 + (((2 * ks + fc) ^ (brow & 7)) << 4);
            uint32_t ah4[4], al4[4], bh4[4], bl4[4];
            LDSM_X4(ah4, sb + aadr);
            LDSM_X4(bh4, slab0 + badr);
            #pragma unroll
            for (int nt = 0; nt < 2; nt++)
                mma_bf16(acc[nt], ah4, bh4[nt], bh4[nt + 2]);
            LDSM_X4(bl4, slab0 + 8192 + badr);
            #pragma unroll
            for (int nt = 0; nt < 2; nt++)
                mma_bf16(acc[nt], ah4, bl4[nt], bl4[nt + 2]);
            LDSM_X4(al4, sb + 4096 + aadr);
            #pragma unroll
            for (int nt = 0; nt < 2; nt++)
                mma_bf16(acc[nt], al4, bh4[nt], bh4[nt + 2]);
        }
        // bias-add: read attn logits directly from gmem, store into L
        // (x8 undoes q/8 pre-scale; exact pow2). Each (row,col) owned by 1 thread.
        #pragma unroll
        for (int nt = 0; nt < 2; nt++) {
            const int col = ck * 64 + wn + nt * 8 + ec;
            const int rbase = mt * 16;
            const float2 a0 = *(const float2*)(arow0 + col);
            const float2 a1 = *(const float2*)(arow1 + col);
            L[(rbase + er) * Sc + col]           = a0.x + 8.f * acc[nt][0];
            L[(rbase + er) * Sc + col + 1]       = a0.y + 8.f * acc[nt][1];
            L[(rbase + er + 8) * Sc + col]       = a1.x + 8.f * acc[nt][2];
            L[(rbase + er + 8) * Sc + col + 1]   = a1.y + 8.f * acc[nt][3];
        }
        __syncthreads();   // all reads of slab done before next overwrite
    }

    // softmax: 32 (it,b) rows over 8 warps = 4 rows per warp
    #pragma unroll
    for (int rr = 0; rr < 4; rr++) {
        const int row = wid * 4 + rr;
        const int it = row >> 3, b = row & 7;
        float v[12];
        float m = -1e30f;
        #pragma unroll
        for (int r = 0; r < 12; r++) { v[r] = L[row * Sc + lane + 32 * r]; m = fmaxf(m, v[r]); }
        #pragma unroll
        for (int o = 16; o > 0; o >>= 1) m = fmaxf(m, __shfl_xor_sync(0xffffffffu, m, o));
        float s = 0.f;
        #pragma unroll
        for (int r = 0; r < 12; r++) { v[r] = __expf(v[r] - m); s += v[r]; }
        #pragma unroll
        for (int o = 16; o > 0; o >>= 1) s += __shfl_xor_sync(0xffffffffu, s, o);
        const float inv = 1.0f / s;
        float* orow = attn + ((size_t)(b * Hc + hh[it]) * Sc + ii[it]) * Sc;
        #pragma unroll
        for (int r = 0; r < 12; r++) orow[lane + 32 * r] = v[r] * inv;
    }
}

// ---------------------------------------------------------------------------
// av HMMA: values = attn(fp32) @ v, 3-pass bf16 split. 64-row tiles, 3 CTA/SM.
// ---------------------------------------------------------------------------
#define AV_AROW 72
#define AV_ATILE (64 * AV_AROW * 4)
#define AV_VTILE 8192
#define AV_STAGE (AV_ATILE + 2 * AV_VTILE)
#define AV_SMEM  (2 * AV_STAGE)

__global__ __launch_bounds__(256, 3) void av_mma_kernel(
    const float* __restrict__ attn,
    const __nv_bfloat16* __restrict__ qkvh, const __nv_bfloat16* __restrict__ qkvl,
    __nv_bfloat16* __restrict__ vh_out, __nv_bfloat16* __restrict__ vl_out)
{
    extern __shared__ char smem[];
    const uint32_t sb = smem_u32(smem);
    float* sA_f = (float*)smem;
    const int tid = threadIdx.x, wid = tid >> 5, lane = tid & 31;
    const int bh = blockIdx.y, b = bh >> 4, h = bh & 15;
    const int i0 = blockIdx.x * 64;

    const float* abase = attn + ((size_t)bh * Sc + i0) * Sc;
    const __nv_bfloat16* vbase_h = qkvh + h * 192 + 128;
    const __nv_bfloat16* vbase_l = qkvl + h * 192 + 128;

    auto issue = [&](int ck) {
        if (ck >= 6) { CP_COMMIT(); return; }
        const uint32_t st = sb + (ck & 1) * AV_STAGE;
        const int j0 = ck * 64;
        for (int idx = tid; idx < 1024; idx += 256) {
            const int row = idx >> 4, c = idx & 15;
            CP_ASYNC16(st + row * (AV_AROW * 4) + c * 16,
                       abase + (size_t)row * Sc + j0 + c * 4);
        }
        for (int idx = tid; idx < 512; idx += 256) {
            const int row = idx >> 3, c = idx & 7;
            const uint32_t sw = row * 128 + ((c ^ (row & 7)) << 4);
            const size_t go = (size_t)(b * Sc + j0 + row) * D3c + c * 8;
            CP_ASYNC16(st + AV_ATILE + sw, vbase_h + go);
            CP_ASYNC16(st + AV_ATILE + AV_VTILE + sw, vbase_l + go);
        }
        CP_COMMIT();
    };

    const int wm = (wid & 1) * 32;
    const int wn = (wid >> 1) * 16;
    const int er = lane >> 2;
    const int ecb = (lane & 3) * 2;
    const int krow = (lane & 7) | ((lane & 16) >> 1);
    const int colc = (lane >> 3) & 1;

    float acc[2][2][4];
    #pragma unroll
    for (int i = 0; i < 2; i++)
        #pragma unroll
        for (int j = 0; j < 2; j++)
            #pragma unroll
            for (int r = 0; r < 4; r++) acc[i][j][r] = 0.f;

    issue(0);
    for (int ck = 0; ck < 6; ck++) {
        issue(ck + 1);
        CP_WAIT1();
        __syncthreads();
        const int stg = (ck & 1);
        float* sA = sA_f + stg * (AV_STAGE / 4);
        const uint32_t vt_h = sb + stg * AV_STAGE + AV_ATILE;
        const uint32_t vt_l = vt_h + AV_VTILE;
        #pragma unroll
        for (int ks = 0; ks < 4; ks++) {
            uint32_t ahf[2][4], alf[2][4];
            #pragma unroll
            for (int mt = 0; mt < 2; mt++) {
                const int r_ = wm + mt * 16 + er;
                const int cb = ks * 16 + ecb;
                float2 x0 = *(float2*)(sA + (size_t)r_ * AV_AROW + cb);
                float2 x1 = *(float2*)(sA + (size_t)(r_ + 8) * AV_AROW + cb);
                float2 x2 = *(float2*)(sA + (size_t)r_ * AV_AROW + cb + 8);
                float2 x3 = *(float2*)(sA + (size_t)(r_ + 8) * AV_AROW + cb + 8);
                pack_hilo(x0.x, x0.y, ahf[mt][0], alf[mt][0]);
                pack_hilo(x1.x, x1.y, ahf[mt][1], alf[mt][1]);
                pack_hilo(x2.x, x2.y, ahf[mt][2], alf[mt][2]);
                pack_hilo(x3.x, x3.y, ahf[mt][3], alf[mt][3]);
            }
            const int vrow = ks * 16 + krow;
            const int vc = (wn >> 3) + colc;
            const uint32_t badr = vrow * 128 + ((vc ^ (vrow & 7)) << 4);
            uint32_t bhf[4], blf[4];
            LDSM_X4_T(bhf, vt_h + badr);
            LDSM_X4_T(blf, vt_l + badr);
            #pragma unroll
            for (int mt = 0; mt < 2; mt++)
                #pragma unroll
                for (int nt = 0; nt < 2; nt++)
                    mma_bf16(acc[mt][nt], ahf[mt], bhf[nt], bhf[nt + 2]);
            #pragma unroll
            for (int mt = 0; mt < 2; mt++)
                #pragma unroll
                for (int nt = 0; nt < 2; nt++)
                    mma_bf16(acc[mt][nt], alf[mt], bhf[nt], bhf[nt + 2]);
            #pragma unroll
            for (int mt = 0; mt < 2; mt++)
                #pragma unroll
                for (int nt = 0; nt < 2; nt++)
                    mma_bf16(acc[mt][nt], ahf[mt], blf[nt], blf[nt + 2]);
        }
        __syncthreads();
    }

    const int ec = (lane & 3) * 2;
    #pragma unroll
    for (int mt = 0; mt < 2; mt++) {
        #pragma unroll
        for (int nt = 0; nt < 2; nt++) {
            const int row = i0 + wm + mt * 16 + er;
            const int col = h * 64 + wn + nt * 8 + ec;
            const size_t o0 = (size_t)(b * Sc + row) * Dc + col;
            const size_t o1 = (size_t)(b * Sc + row + 8) * Dc + col;
            split2(acc[mt][nt][0], acc[mt][nt][1], vh_out + o0, vl_out + o0);
            split2(acc[mt][nt][2], acc[mt][nt][3], vh_out + o1, vl_out + o1);
        }
    }
}

// ---------------------------------------------------------------------------
extern "C" void kernel_launch(void* const* d_in, const int* in_sizes, int n_in,
                              void* d_out, int out_size)
{
    const float* x     = (const float*)d_in[0];
    const float* qkv_w = (const float*)d_in[1];
    const float* qkv_b = (const float*)d_in[2];
    const float* out_w = (const float*)d_in[3];
    const float* out_b = (const float*)d_in[4];
    const float* rpe   = (const float*)d_in[5];

    float* attnscr;
    __nv_bfloat16 *ah, *al, *wqh, *wql, *woh, *wol, *qkvh, *qkvl, *rpeh, *rpel;
    cudaGetSymbolAddress((void**)&attnscr, g_attn);
    cudaGetSymbolAddress((void**)&ah, g_ah);
    cudaGetSymbolAddress((void**)&al, g_al);
    cudaGetSymbolAddress((void**)&wqh, g_wqh);
    cudaGetSymbolAddress((void**)&wql, g_wql);
    cudaGetSymbolAddress((void**)&woh, g_woh);
    cudaGetSymbolAddress((void**)&wol, g_wol);
    cudaGetSymbolAddress((void**)&qkvh, g_qkvh);
    cudaGetSymbolAddress((void**)&qkvl, g_qkvl);
    cudaGetSymbolAddress((void**)&rpeh, g_rpeh);
    cudaGetSymbolAddress((void**)&rpel, g_rpel);

    float* out = (float*)d_out;
    const long OUT_E = (long)BSc * Dc;
    const long ATT_E = (long)Bc * Hc * Sc * Sc;
    float* attn = ((long)out_size >= OUT_E + ATT_E) ? (out + OUT_E) : attnscr;

    cudaFuncSetAttribute(mma_gemm_kernel,
                         cudaFuncAttributeMaxDynamicSharedMemorySize, GSMEM);
    cudaFuncSetAttribute(out_gemm_kernel,
                         cudaFuncAttributeMaxDynamicSharedMemorySize, OSMEM);
    cudaFuncSetAttribute(qk_mma_kernel,
                         cudaFuncAttributeMaxDynamicSharedMemorySize, QK_SMEM);
    cudaFuncSetAttribute(rpe_mma_softmax_kernel,
                         cudaFuncAttributeMaxDynamicSharedMemorySize, RPE_SMEM);
    cudaFuncSetAttribute(av_mma_kernel,
                         cudaFuncAttributeMaxDynamicSharedMemorySize, AV_SMEM);

    // 0) fused prep: split x + weights + rpe table
    prep_kernel<<<8191, 256>>>(x, ah, al, qkv_w, wqh, wql, out_w, woh, wol,
                               rpe, rpeh, rpel);
    // 1) qkv: emit bf16 hi/lo (q cols pre-scaled 1/8)
    mma_gemm_kernel<<<dim3(D3c / 128, BSc / 128), 256, GSMEM>>>(
        ah, al, wqh, wql, qkv_b, nullptr, qkvh, qkvl, 1, BSc, D3c, Dc);
    // 2) logits = (q/8) . k
    qk_mma_kernel<<<dim3(3, 3, Bc * Hc), 256, QK_SMEM>>>(qkvh, qkvl, attn);
    // 3+4) rpe bias via HMMA + softmax (direct-gmem bias add)
    rpe_mma_softmax_kernel<<<dim3(24 * 31, 4), 256, RPE_SMEM>>>(
        qkvh, qkvl, rpeh, rpel, attn);
    // 5) values = attn @ v -> bf16 hi/lo
    av_mma_kernel<<<dim3(6, Bc * Hc), 256, AV_SMEM>>>(attn, qkvh, qkvl, ah, al);
    // 6) out = values @ out_w + out_b
    out_gemm_kernel<<<dim3(Dc / 128, BSc / 64), 256, OSMEM>>>(
        ah, al, woh, wol, out_b, out, BSc, Dc, Dc);
}